// round 1
// baseline (speedup 1.0000x reference)
#include <cuda_runtime.h>
#include <cstdint>

#define BATCH 2
#define SEQ   4096
#define EMB   768
#define NH    12
#define HD    64
#define M_ROWS (BATCH*SEQ)   /* 8192 */

// Scratch (no allocations allowed) — Q/K/V in [B,H,S,D], attention out in [B,S,E]
__device__ float g_q[(size_t)BATCH*NH*SEQ*HD];
__device__ float g_k[(size_t)BATCH*NH*SEQ*HD];
__device__ float g_v[(size_t)BATCH*NH*SEQ*HD];
__device__ float g_att[(size_t)M_ROWS*EMB];

__device__ __forceinline__ float tf32r(float x){
    uint32_t u;
    asm("cvt.rna.tf32.f32 %0, %1;" : "=r"(u) : "f"(x));
    return __uint_as_float(u);
}

__device__ __forceinline__ void mma8(float c[4], const uint32_t a[4], const uint32_t b[2]){
    asm volatile(
      "mma.sync.aligned.m16n8k8.row.col.f32.tf32.tf32.f32 "
      "{%0,%1,%2,%3},{%4,%5,%6,%7},{%8,%9},{%0,%1,%2,%3};\n"
      : "+f"(c[0]), "+f"(c[1]), "+f"(c[2]), "+f"(c[3])
      : "r"(a[0]), "r"(a[1]), "r"(a[2]), "r"(a[3]), "r"(b[0]), "r"(b[1]));
}

__device__ __forceinline__ void scatter_qkv(int m, int n, float v){
    int which = n / EMB;
    int e = n - which*EMB;
    int h = e >> 6, d = e & 63;
    int b = m >> 12, s = m & (SEQ-1);
    size_t idx = (((size_t)(b*NH + h))*SEQ + s)*HD + d;
    float* dst = (which==0) ? g_q : (which==1) ? g_k : g_v;
    dst[idx] = v;
}

// C[M,N] = A[M,768] * B[N,768]^T ; MODE 0: A=x, scatter into g_q/g_k/g_v
//                                  MODE 1: A=g_att, C=out (+bias)
template<int MODE>
__global__ __launch_bounds__(256) void gemm_tf32(const float* __restrict__ Ain,
                                                 const float* __restrict__ B,
                                                 float* __restrict__ C,
                                                 const float* __restrict__ bias){
    const int K = EMB;
    const float* A = (MODE==0) ? Ain : g_att;
    __shared__ float sA[128][36];
    __shared__ float sB[128][36];
    int tid  = threadIdx.x;
    int m0   = blockIdx.y*128, n0 = blockIdx.x*128;
    int lane = tid & 31, wid = tid >> 5;
    int wm   = (wid & 3) * 32, wn = (wid >> 2) * 64;
    int gid  = lane >> 2, tig = lane & 3;

    float acc[2][8][4];
    #pragma unroll
    for (int i=0;i<2;i++)
        #pragma unroll
        for (int nt=0;nt<8;nt++)
            #pragma unroll
            for (int j=0;j<4;j++) acc[i][nt][j]=0.f;

    int lr = tid >> 3;
    int lc = (tid & 7) * 4;
    for (int kk=0; kk<K; kk+=32){
        #pragma unroll
        for (int p=0;p<4;p++){
            int row = p*32 + lr;
            float4 va = *(const float4*)(A + (size_t)(m0+row)*K + kk + lc);
            sA[row][lc+0]=tf32r(va.x); sA[row][lc+1]=tf32r(va.y);
            sA[row][lc+2]=tf32r(va.z); sA[row][lc+3]=tf32r(va.w);
            float4 vb = *(const float4*)(B + (size_t)(n0+row)*K + kk + lc);
            sB[row][lc+0]=tf32r(vb.x); sB[row][lc+1]=tf32r(vb.y);
            sB[row][lc+2]=tf32r(vb.z); sB[row][lc+3]=tf32r(vb.w);
        }
        __syncthreads();
        #pragma unroll
        for (int k8=0;k8<4;k8++){
            int kc = k8*8;
            uint32_t a[2][4];
            #pragma unroll
            for (int i=0;i<2;i++){
                int r0 = wm + i*16 + gid;
                a[i][0] = __float_as_uint(sA[r0  ][kc+tig]);
                a[i][1] = __float_as_uint(sA[r0+8][kc+tig]);
                a[i][2] = __float_as_uint(sA[r0  ][kc+tig+4]);
                a[i][3] = __float_as_uint(sA[r0+8][kc+tig+4]);
            }
            #pragma unroll
            for (int nt=0;nt<8;nt++){
                int cn = wn + nt*8 + gid;
                uint32_t b[2];
                b[0] = __float_as_uint(sB[cn][kc+tig]);
                b[1] = __float_as_uint(sB[cn][kc+tig+4]);
                mma8(acc[0][nt], a[0], b);
                mma8(acc[1][nt], a[1], b);
            }
        }
        __syncthreads();
    }
    #pragma unroll
    for (int i=0;i<2;i++){
        int r0 = m0 + wm + i*16 + gid;
        #pragma unroll
        for (int nt=0;nt<8;nt++){
            int n = n0 + wn + nt*8 + tig*2;
            if (MODE==0){
                scatter_qkv(r0,   n,   acc[i][nt][0]);
                scatter_qkv(r0,   n+1, acc[i][nt][1]);
                scatter_qkv(r0+8, n,   acc[i][nt][2]);
                scatter_qkv(r0+8, n+1, acc[i][nt][3]);
            } else {
                C[(size_t)r0*EMB + n]       = acc[i][nt][0] + bias[n];
                C[(size_t)r0*EMB + n+1]     = acc[i][nt][1] + bias[n+1];
                C[(size_t)(r0+8)*EMB + n]   = acc[i][nt][2] + bias[n];
                C[(size_t)(r0+8)*EMB + n+1] = acc[i][nt][3] + bias[n+1];
            }
        }
    }
}

// Flash attention: one CTA = 128 q-rows of one (b,h); KV tiles of 64.
// 8 warps * 16 q-rows. QK^T and P*V via tf32 mma; softmax state in registers.
#define QT   128
#define KT   64
#define LDS_ (HD+4)   /* 68: stride ≡ 4 mod 32 -> conflict-free frag loads */

__global__ __launch_bounds__(256) void attn_kernel(){
    extern __shared__ float sm[];
    float* sQ = sm;                    // 128 x 68
    float* sK = sQ + QT*LDS_;          // 64 x 68
    float* sV = sK + KT*LDS_;          // 64 x 68
    float* sP = sV + KT*LDS_;          // 8 x 16 x 68

    int tid = threadIdx.x, lane = tid & 31, wid = tid >> 5;
    int gid = lane >> 2, tig = lane & 3;
    int qt = blockIdx.x, bh = blockIdx.y;

    const float* Qp = g_q + (size_t)bh*SEQ*HD;
    const float* Kp = g_k + (size_t)bh*SEQ*HD;
    const float* Vp = g_v + (size_t)bh*SEQ*HD;
    const float scale = 0.125f;  // 64^-0.5

    // load Q tile (pre-scaled, tf32-rounded)
    {
        int r = tid >> 4, c4 = (tid & 15) * 4;
        #pragma unroll
        for (int p=0;p<8;p++){
            int row = p*16 + r;
            float4 v = *(const float4*)(Qp + (size_t)(qt*QT+row)*HD + c4);
            sQ[row*LDS_+c4+0]=tf32r(v.x*scale); sQ[row*LDS_+c4+1]=tf32r(v.y*scale);
            sQ[row*LDS_+c4+2]=tf32r(v.z*scale); sQ[row*LDS_+c4+3]=tf32r(v.w*scale);
        }
    }

    float m0r = -1e30f, m1r = -1e30f, l0 = 0.f, l1 = 0.f;
    float o[8][4];
    #pragma unroll
    for (int nt=0;nt<8;nt++){ o[nt][0]=0;o[nt][1]=0;o[nt][2]=0;o[nt][3]=0; }

    float* pw = sP + wid*16*LDS_;
    int r0q = wid*16 + gid;

    for (int kt=0; kt<SEQ/KT; kt++){
        __syncthreads();
        {   // load K,V tiles
            int r = tid >> 4, c4 = (tid & 15) * 4;
            #pragma unroll
            for (int p=0;p<4;p++){
                int row = p*16 + r;
                float4 vk = *(const float4*)(Kp + (size_t)(kt*KT+row)*HD + c4);
                sK[row*LDS_+c4+0]=tf32r(vk.x); sK[row*LDS_+c4+1]=tf32r(vk.y);
                sK[row*LDS_+c4+2]=tf32r(vk.z); sK[row*LDS_+c4+3]=tf32r(vk.w);
                float4 vv = *(const float4*)(Vp + (size_t)(kt*KT+row)*HD + c4);
                sV[row*LDS_+c4+0]=tf32r(vv.x); sV[row*LDS_+c4+1]=tf32r(vv.y);
                sV[row*LDS_+c4+2]=tf32r(vv.z); sV[row*LDS_+c4+3]=tf32r(vv.w);
            }
        }
        __syncthreads();

        // S = Q K^T  (16 x 64 per warp)
        float s[8][4];
        #pragma unroll
        for (int nt=0;nt<8;nt++){ s[nt][0]=0;s[nt][1]=0;s[nt][2]=0;s[nt][3]=0; }
        #pragma unroll
        for (int k8=0;k8<8;k8++){
            int kc = k8*8;
            uint32_t a[4];
            a[0] = __float_as_uint(sQ[(r0q  )*LDS_ + kc+tig]);
            a[1] = __float_as_uint(sQ[(r0q+8)*LDS_ + kc+tig]);
            a[2] = __float_as_uint(sQ[(r0q  )*LDS_ + kc+tig+4]);
            a[3] = __float_as_uint(sQ[(r0q+8)*LDS_ + kc+tig+4]);
            #pragma unroll
            for (int nt=0;nt<8;nt++){
                int cn = nt*8 + gid;
                uint32_t b[2];
                b[0] = __float_as_uint(sK[cn*LDS_ + kc+tig]);
                b[1] = __float_as_uint(sK[cn*LDS_ + kc+tig+4]);
                mma8(s[nt], a, b);
            }
        }

        // online softmax (rows r0q and r0q+8)
        float mx0 = s[0][0], mx1 = s[0][2];
        #pragma unroll
        for (int nt=0;nt<8;nt++){
            mx0 = fmaxf(mx0, fmaxf(s[nt][0], s[nt][1]));
            mx1 = fmaxf(mx1, fmaxf(s[nt][2], s[nt][3]));
        }
        mx0 = fmaxf(mx0, __shfl_xor_sync(0xffffffffu, mx0, 1));
        mx0 = fmaxf(mx0, __shfl_xor_sync(0xffffffffu, mx0, 2));
        mx1 = fmaxf(mx1, __shfl_xor_sync(0xffffffffu, mx1, 1));
        mx1 = fmaxf(mx1, __shfl_xor_sync(0xffffffffu, mx1, 2));
        float mn0 = fmaxf(m0r, mx0), mn1 = fmaxf(m1r, mx1);
        float f0 = __expf(m0r - mn0), f1 = __expf(m1r - mn1);
        float sum0 = 0.f, sum1 = 0.f;
        #pragma unroll
        for (int nt=0;nt<8;nt++){
            s[nt][0] = __expf(s[nt][0]-mn0); s[nt][1] = __expf(s[nt][1]-mn0);
            s[nt][2] = __expf(s[nt][2]-mn1); s[nt][3] = __expf(s[nt][3]-mn1);
            sum0 += s[nt][0] + s[nt][1];
            sum1 += s[nt][2] + s[nt][3];
        }
        sum0 += __shfl_xor_sync(0xffffffffu, sum0, 1);
        sum0 += __shfl_xor_sync(0xffffffffu, sum0, 2);
        sum1 += __shfl_xor_sync(0xffffffffu, sum1, 1);
        sum1 += __shfl_xor_sync(0xffffffffu, sum1, 2);
        l0 = l0*f0 + sum0;  l1 = l1*f1 + sum1;
        m0r = mn0;          m1r = mn1;
        #pragma unroll
        for (int nt=0;nt<8;nt++){
            o[nt][0]*=f0; o[nt][1]*=f0; o[nt][2]*=f1; o[nt][3]*=f1;
        }

        // stage P (C-fragment layout) to smem in tf32
        #pragma unroll
        for (int nt=0;nt<8;nt++){
            int cc = nt*8 + tig*2;
            pw[(gid  )*LDS_ + cc  ] = tf32r(s[nt][0]);
            pw[(gid  )*LDS_ + cc+1] = tf32r(s[nt][1]);
            pw[(gid+8)*LDS_ + cc  ] = tf32r(s[nt][2]);
            pw[(gid+8)*LDS_ + cc+1] = tf32r(s[nt][3]);
        }
        __syncwarp();

        // O += P V   (16 x 64 per warp, k = 64 kv positions)
        #pragma unroll
        for (int k8=0;k8<8;k8++){
            int kc = k8*8;
            uint32_t a[4];
            a[0] = __float_as_uint(pw[(gid  )*LDS_ + kc+tig]);
            a[1] = __float_as_uint(pw[(gid+8)*LDS_ + kc+tig]);
            a[2] = __float_as_uint(pw[(gid  )*LDS_ + kc+tig+4]);
            a[3] = __float_as_uint(pw[(gid+8)*LDS_ + kc+tig+4]);
            #pragma unroll
            for (int nt=0;nt<8;nt++){
                int cn = nt*8 + gid;
                uint32_t b[2];
                b[0] = __float_as_uint(sV[(kc+tig  )*LDS_ + cn]);
                b[1] = __float_as_uint(sV[(kc+tig+4)*LDS_ + cn]);
                mma8(o[nt], a, b);
            }
        }
        __syncwarp();
    }

    // epilogue -> g_att in [B,S,E]
    float rl0 = 1.f/l0, rl1 = 1.f/l1;
    int b = bh / NH, h = bh % NH;
    int rg0 = qt*QT + wid*16 + gid, rg1 = rg0 + 8;
    size_t base0 = ((size_t)b*SEQ + rg0)*EMB + h*HD;
    size_t base1 = ((size_t)b*SEQ + rg1)*EMB + h*HD;
    #pragma unroll
    for (int nt=0;nt<8;nt++){
        int d = nt*8 + tig*2;
        g_att[base0 + d]   = o[nt][0]*rl0;
        g_att[base0 + d+1] = o[nt][1]*rl0;
        g_att[base1 + d]   = o[nt][2]*rl1;
        g_att[base1 + d+1] = o[nt][3]*rl1;
    }
}

extern "C" void kernel_launch(void* const* d_in, const int* in_sizes, int n_in,
                              void* d_out, int out_size){
    (void)in_sizes; (void)n_in; (void)out_size;
    const float* x     = (const float*)d_in[0];
    const float* Wqkv  = (const float*)d_in[1];
    const float* Wproj = (const float*)d_in[2];
    const float* bproj = (const float*)d_in[3];
    float* out = (float*)d_out;

    const int attn_smem = (QT*LDS_ + 2*KT*LDS_ + 8*16*LDS_) * (int)sizeof(float); // 104448
    cudaFuncSetAttribute(attn_kernel, cudaFuncAttributeMaxDynamicSharedMemorySize, attn_smem);

    // 1) QKV projection: [8192,768] x [2304,768]^T -> scatter Q/K/V [B,H,S,D]
    gemm_tf32<0><<<dim3(3*EMB/128, M_ROWS/128), 256>>>(x, Wqkv, nullptr, nullptr);
    // 2) flash attention per (q-tile, b*h)
    attn_kernel<<<dim3(SEQ/QT, BATCH*NH), 256, attn_smem>>>();
    // 3) output projection + bias
    gemm_tf32<1><<<dim3(EMB/128, M_ROWS/128), 256>>>(nullptr, Wproj, out, bproj);
}